// round 1
// baseline (speedup 1.0000x reference)
#include <cuda_runtime.h>
#include <cuda_bf16.h>

// Modulated deformable conv: N=8, Cin=256, H=W=56, Cout=256, 3x3, stride 1, pad 1.
// Fused deformable-im2col + SIMT fp32 GEMM.
//   M = N*H*W = 25088 pixels, Ngemm = Cout = 256, Kgemm = 9*256 = 2304.
// Tile: BM=64 pixels x BN=128 couts per CTA, BK=32 (cin chunk within one tap).
// Per-CTA precompute: 4 bilinear base addresses + mask-folded weights per (pixel, tap).

#define CIN   256
#define COUT  256
#define HH    56
#define WW    56
#define NB    8
#define KTAPS 9
#define HWSZ  (HH*WW)          // 3136
#define CHW   (CIN*HWSZ)
#define MTOT  (NB*HWSZ)        // 25088 = 392 * 64 exactly

#define BM 64
#define BN 128
#define BK 32
#define NT 256

// Transposed weight scratch: wT[k][c][o]  (9*256*256 floats = 2.25 MB)
__device__ float g_wT[KTAPS * CIN * COUT];

__global__ void transpose_w_kernel(const float* __restrict__ w) {
    int i = blockIdx.x * blockDim.x + threadIdx.x;
    if (i >= KTAPS * CIN * COUT) return;
    int o = i % COUT;
    int c = (i / COUT) % CIN;
    int k = i / (COUT * CIN);
    // weight layout: [Cout][Cin][kh][kw] -> w[o][c][k]
    g_wT[i] = w[(o * CIN + c) * KTAPS + k];
}

__global__ __launch_bounds__(NT) void mdcn_kernel(
    const float* __restrict__ x,       // [N, Cin, H, W]
    const float* __restrict__ offset,  // [N, 18, H, W]
    const float* __restrict__ mask,    // [N, 9, H, W]
    const float* __restrict__ bias,    // [Cout]
    float* __restrict__ out)           // [N, Cout, H, W]
{
    __shared__ int   s_base[BM][KTAPS][4];
    __shared__ float s_wgt [BM][KTAPS][4];
    __shared__ float As[BK][BM];       // v[cin_local][pixel]
    __shared__ float Bs[BK][BN];       // w[cin_local][cout_local]

    const int p0  = blockIdx.x * BM;       // first pixel of tile
    const int ob  = blockIdx.y * BN;       // first cout of tile
    const int tid = threadIdx.x;

    // ---- Precompute bilinear taps for each (pixel, tap) ----
    for (int it = tid; it < BM * KTAPS; it += NT) {
        int p = it / KTAPS;
        int k = it - p * KTAPS;
        int pg = p0 + p;
        int n  = pg / HWSZ;
        int hw = pg - n * HWSZ;
        int h  = hw / WW;
        int w  = hw - h * WW;

        float dy = offset[((n * 18 + 2 * k    ) * HH + h) * WW + w];
        float dx = offset[((n * 18 + 2 * k + 1) * HH + h) * WW + w];
        float m  = mask  [((n * 9  + k        ) * HH + h) * WW + w];

        float py = dy + (float)(k / 3) + (float)(h - 1);
        float px = dx + (float)(k % 3) + (float)(w - 1);
        float y0f = floorf(py);
        float x0f = floorf(px);
        float wy1 = py - y0f, wx1 = px - x0f;
        float wy0 = 1.0f - wy1, wx0 = 1.0f - wx1;
        int y0 = (int)y0f;
        int x0 = (int)x0f;
        int nbase = n * CHW;

        float tw[4] = { wy0 * wx0, wy0 * wx1, wy1 * wx0, wy1 * wx1 };
        #pragma unroll
        for (int t = 0; t < 4; ++t) {
            int yy = y0 + (t >> 1);
            int xx = x0 + (t & 1);
            bool valid = (yy >= 0) && (yy < HH) && (xx >= 0) && (xx < WW);
            int yc = min(max(yy, 0), HH - 1);
            int xc = min(max(xx, 0), WW - 1);
            s_base[p][k][t] = nbase + yc * WW + xc;
            s_wgt [p][k][t] = valid ? tw[t] * m : 0.0f;
        }
    }
    __syncthreads();

    float acc[4][8];
    #pragma unroll
    for (int r = 0; r < 4; ++r)
        #pragma unroll
        for (int j = 0; j < 8; ++j) acc[r][j] = 0.0f;

    const int ty = tid >> 4;   // 0..15 -> pixel group (4 pixels each)
    const int tx = tid & 15;   // 0..15 -> cout group (8 couts each)

    const int pA  = tid & 63;  // pixel this thread gathers for
    const int cgA = tid >> 6;  // 0..3 -> 8 cin values each

    for (int step = 0; step < 72; ++step) {
        const int k  = step >> 3;          // tap 0..8
        const int c0 = (step & 7) * BK;    // cin base

        // ---- Fill B tile (coalesced from transposed weight) ----
        {
            const float* src = &g_wT[(k * CIN + c0) * COUT + ob];
            #pragma unroll
            for (int i = tid; i < BK * BN; i += NT) {
                int ci = i >> 7;           // /128
                int oi = i & 127;
                Bs[ci][oi] = src[ci * COUT + oi];
            }
        }

        // ---- Fill A tile: on-the-fly deformable gather ----
        {
            int   b0 = s_base[pA][k][0], b1 = s_base[pA][k][1];
            int   b2 = s_base[pA][k][2], b3 = s_base[pA][k][3];
            float w0 = s_wgt [pA][k][0], w1 = s_wgt [pA][k][1];
            float w2 = s_wgt [pA][k][2], w3 = s_wgt [pA][k][3];
            #pragma unroll
            for (int j = 0; j < 8; ++j) {
                int c    = c0 + cgA * 8 + j;
                int coff = c * HWSZ;
                float v;
                v = w0 * x[b0 + coff];
                v = fmaf(w1, x[b1 + coff], v);
                v = fmaf(w2, x[b2 + coff], v);
                v = fmaf(w3, x[b3 + coff], v);
                As[cgA * 8 + j][pA] = v;
            }
        }
        __syncthreads();

        // ---- Compute ----
        #pragma unroll
        for (int kk = 0; kk < BK; ++kk) {
            float4 a  = *(const float4*)&As[kk][ty * 4];
            float4 bA = *(const float4*)&Bs[kk][tx * 8];
            float4 bB = *(const float4*)&Bs[kk][tx * 8 + 4];
            float av[4] = { a.x, a.y, a.z, a.w };
            float bv[8] = { bA.x, bA.y, bA.z, bA.w, bB.x, bB.y, bB.z, bB.w };
            #pragma unroll
            for (int r = 0; r < 4; ++r)
                #pragma unroll
                for (int j = 0; j < 8; ++j)
                    acc[r][j] = fmaf(av[r], bv[j], acc[r][j]);
        }
        __syncthreads();
    }

    // ---- Epilogue ----
    #pragma unroll
    for (int r = 0; r < 4; ++r) {
        int pg = p0 + ty * 4 + r;
        int n  = pg / HWSZ;
        int hw = pg - n * HWSZ;
        int obase = n * COUT * HWSZ + hw;
        #pragma unroll
        for (int j = 0; j < 8; ++j) {
            int o = ob + tx * 8 + j;
            out[obase + o * HWSZ] = acc[r][j] + bias[o];
        }
    }
}

extern "C" void kernel_launch(void* const* d_in, const int* in_sizes, int n_in,
                              void* d_out, int out_size) {
    const float* x      = (const float*)d_in[0];
    const float* offset = (const float*)d_in[1];
    const float* mask   = (const float*)d_in[2];
    const float* weight = (const float*)d_in[3];
    const float* bias   = (const float*)d_in[4];
    float* out = (float*)d_out;

    transpose_w_kernel<<<(KTAPS * CIN * COUT + 255) / 256, 256>>>(weight);

    dim3 grid(MTOT / BM, COUT / BN);   // (392, 2)
    mdcn_kernel<<<grid, NT>>>(x, offset, mask, bias, out);
}

// round 3
// speedup vs baseline: 1.5968x; 1.5968x over previous
#include <cuda_runtime.h>
#include <cuda_bf16.h>

// Modulated deformable conv, fused deformable-im2col + SIMT fp32 GEMM.
// R2: x pre-transposed to NHWC (vectorized float4 gather), BN=256 (no gather
// duplication), contiguous B-tile fill, broadcast a-loads.
//   M = N*H*W = 25088, Ngemm = Cout = 256, Kgemm = 9*256 = 2304.

#define CIN   256
#define COUT  256
#define HH    56
#define WW    56
#define NB    8
#define KTAPS 9
#define HWSZ  (HH*WW)          // 3136
#define MTOT  (NB*HWSZ)        // 25088 = 392 * 64

#define BM 64
#define BN 256
#define BK 16
#define NT 256
#define AP 24                  // As row stride (pad for alignment + banks)

// Scratch (device globals: no allocation allowed)
__device__ float g_wT[KTAPS * CIN * COUT];            // [k][c][o], 2.25 MB
__device__ float g_xn[NB * HH * WW * CIN];            // NHWC, 25.7 MB

__global__ void transpose_w_kernel(const float* __restrict__ w) {
    int i = blockIdx.x * blockDim.x + threadIdx.x;
    if (i >= KTAPS * CIN * COUT) return;
    int o = i % COUT;
    int c = (i / COUT) % CIN;
    int k = i / (COUT * CIN);
    g_wT[i] = w[(o * CIN + c) * KTAPS + k];           // w[o][c][k]
}

// NCHW -> NHWC tiled transpose (32 c x 32 w tiles through smem)
__global__ void transpose_x_kernel(const float* __restrict__ x) {
    __shared__ float tile[32][33];
    int wT = blockIdx.x;           // 0..1
    int cT = blockIdx.y;           // 0..7
    int nh = blockIdx.z;           // 0..447
    int n = nh / HH, h = nh - n * HH;
    int tx = threadIdx.x, ty = threadIdx.y;

    #pragma unroll
    for (int i = 0; i < 4; ++i) {
        int c = cT * 32 + ty + i * 8;
        int w = wT * 32 + tx;
        if (w < WW)
            tile[ty + i * 8][tx] = x[((n * CIN + c) * HH + h) * WW + w];
    }
    __syncthreads();
    #pragma unroll
    for (int i = 0; i < 4; ++i) {
        int w = wT * 32 + ty + i * 8;
        int c = cT * 32 + tx;
        if (w < WW)
            g_xn[((n * HH + h) * WW + w) * CIN + c] = tile[tx][ty + i * 8];
    }
}

__global__ __launch_bounds__(NT, 2) void mdcn_kernel(
    const float* __restrict__ offset,  // [N, 18, H, W]
    const float* __restrict__ mask,    // [N, 9, H, W]
    const float* __restrict__ bias,    // [Cout]
    float* __restrict__ out)           // [N, Cout, H, W]
{
    __shared__ int   s_base[BM][KTAPS][4];
    __shared__ float s_wgt [BM][KTAPS][4];
    __shared__ float As[BM][AP];            // v[pixel][cin_local]
    __shared__ float Bs[BK][BN];            // w[cin_local][cout]

    const int p0  = blockIdx.x * BM;
    const int tid = threadIdx.x;

    // ---- Precompute bilinear taps per (pixel, tap) ----
    for (int it = tid; it < BM * KTAPS; it += NT) {
        int p = it / KTAPS;
        int k = it - p * KTAPS;
        int pg = p0 + p;
        int n  = pg / HWSZ;
        int hw = pg - n * HWSZ;
        int h  = hw / WW;
        int w  = hw - h * WW;

        float dy = offset[((n * 18 + 2 * k    ) * HH + h) * WW + w];
        float dx = offset[((n * 18 + 2 * k + 1) * HH + h) * WW + w];
        float m  = mask  [((n * 9  + k        ) * HH + h) * WW + w];

        float py = dy + (float)(k / 3) + (float)(h - 1);
        float px = dx + (float)(k % 3) + (float)(w - 1);
        float y0f = floorf(py);
        float x0f = floorf(px);
        float wy1 = py - y0f, wx1 = px - x0f;
        float wy0 = 1.0f - wy1, wx0 = 1.0f - wx1;
        int y0 = (int)y0f;
        int x0 = (int)x0f;

        float tw[4] = { wy0 * wx0, wy0 * wx1, wy1 * wx0, wy1 * wx1 };
        #pragma unroll
        for (int t = 0; t < 4; ++t) {
            int yy = y0 + (t >> 1);
            int xx = x0 + (t & 1);
            bool valid = (yy >= 0) && (yy < HH) && (xx >= 0) && (xx < WW);
            int yc = min(max(yy, 0), HH - 1);
            int xc = min(max(xx, 0), WW - 1);
            s_base[p][k][t] = ((n * HH + yc) * WW + xc) * CIN;   // NHWC base
            s_wgt [p][k][t] = valid ? tw[t] * m : 0.0f;
        }
    }
    __syncthreads();

    float acc[8][8];
    #pragma unroll
    for (int r = 0; r < 8; ++r)
        #pragma unroll
        for (int j = 0; j < 8; ++j) acc[r][j] = 0.0f;

    const int tx = tid & 31;    // cout group: 8 couts
    const int ty = tid >> 5;    // pixel group: 8 pixels

    const int pA  = tid >> 2;   // gather pixel (0..63)
    const int cqA = tid & 3;    // gather cin quad (0..3) within BK

    for (int step = 0; step < (KTAPS * CIN / BK); ++step) {   // 144
        const int k  = step >> 4;           // tap
        const int c0 = (step & 15) * BK;    // cin base

        // ---- B tile: contiguous 16KB copy from wT ----
        {
            const float4* src = (const float4*)&g_wT[(k * CIN + c0) * COUT];
            float4* dst = (float4*)&Bs[0][0];
            #pragma unroll
            for (int i = tid; i < BK * BN / 4; i += NT)
                dst[i] = src[i];
        }

        // ---- A tile: vectorized deformable gather from NHWC ----
        {
            int   b0 = s_base[pA][k][0], b1 = s_base[pA][k][1];
            int   b2 = s_base[pA][k][2], b3 = s_base[pA][k][3];
            float w0 = s_wgt [pA][k][0], w1 = s_wgt [pA][k][1];
            float w2 = s_wgt [pA][k][2], w3 = s_wgt [pA][k][3];
            int c = c0 + cqA * 4;
            float4 v0 = *(const float4*)&g_xn[b0 + c];
            float4 v1 = *(const float4*)&g_xn[b1 + c];
            float4 v2 = *(const float4*)&g_xn[b2 + c];
            float4 v3 = *(const float4*)&g_xn[b3 + c];
            float4 v;
            v.x = fmaf(w3, v3.x, fmaf(w2, v2.x, fmaf(w1, v1.x, w0 * v0.x)));
            v.y = fmaf(w3, v3.y, fmaf(w2, v2.y, fmaf(w1, v1.y, w0 * v0.y)));
            v.z = fmaf(w3, v3.z, fmaf(w2, v2.z, fmaf(w1, v1.z, w0 * v0.z)));
            v.w = fmaf(w3, v3.w, fmaf(w2, v2.w, fmaf(w1, v1.w, w0 * v0.w)));
            *(float4*)&As[pA][cqA * 4] = v;
        }
        __syncthreads();

        // ---- Compute 8x8 microtile ----
        #pragma unroll
        for (int kk = 0; kk < BK; kk += 2) {
            float2 a2[8];
            #pragma unroll
            for (int r = 0; r < 8; ++r)
                a2[r] = *(const float2*)&As[ty * 8 + r][kk];
            #pragma unroll
            for (int q = 0; q < 2; ++q) {
                float4 bA = *(const float4*)&Bs[kk + q][tx * 8];
                float4 bB = *(const float4*)&Bs[kk + q][tx * 8 + 4];
                float bv[8] = { bA.x, bA.y, bA.z, bA.w, bB.x, bB.y, bB.z, bB.w };
                #pragma unroll
                for (int r = 0; r < 8; ++r) {
                    float a = q ? a2[r].y : a2[r].x;
                    #pragma unroll
                    for (int j = 0; j < 8; ++j)
                        acc[r][j] = fmaf(a, bv[j], acc[r][j]);
                }
            }
        }
        __syncthreads();
    }

    // ---- Epilogue ----
    #pragma unroll
    for (int j = 0; j < 8; ++j) {
        int o = tx * 8 + j;
        float bv = bias[o];
        #pragma unroll
        for (int r = 0; r < 8; ++r) {
            int pg = p0 + ty * 8 + r;
            int n  = pg / HWSZ;
            int hw = pg - n * HWSZ;
            out[(n * COUT + o) * HWSZ + hw] = acc[r][j] + bv;
        }
    }
}

extern "C" void kernel_launch(void* const* d_in, const int* in_sizes, int n_in,
                              void* d_out, int out_size) {
    const float* x      = (const float*)d_in[0];
    const float* offset = (const float*)d_in[1];
    const float* mask   = (const float*)d_in[2];
    const float* weight = (const float*)d_in[3];
    const float* bias   = (const float*)d_in[4];
    float* out = (float*)d_out;

    transpose_w_kernel<<<(KTAPS * CIN * COUT + 255) / 256, 256>>>(weight);
    {
        dim3 grid(2, 8, NB * HH);
        dim3 block(32, 8);
        transpose_x_kernel<<<grid, block>>>(x);
    }
    mdcn_kernel<<<MTOT / BM, NT>>>(offset, mask, bias, out);
}

// round 4
// speedup vs baseline: 2.6492x; 1.6591x over previous
#include <cuda_runtime.h>
#include <cuda_bf16.h>

// Modulated deformable conv, fused deformable-im2col + fp32x2 GEMM.
// R4: packed fma.rn.f32x2 (2x FMA throughput), double-buffered smem pipeline
// (1 sync/step), cp.async B-fill, taps in registers.
//   M = N*H*W = 25088, Ngemm = Cout = 256, Kgemm = 9*256 = 2304.

#define CIN   256
#define COUT  256
#define HH    56
#define WW    56
#define NB    8
#define KTAPS 9
#define HWSZ  (HH*WW)          // 3136 = 49*64
#define MTOT  (NB*HWSZ)        // 25088

#define BM 64
#define BN 256
#define BK 16
#define NT 256
#define AP 24                  // As row stride (floats)
#define NSTEP (KTAPS*CIN/BK)   // 144

typedef unsigned long long u64;

__device__ float g_wT[KTAPS * CIN * COUT];   // [k][c][o], 2.25 MB
__device__ float g_xn[NB * HH * WW * CIN];   // NHWC, 25.7 MB

__global__ void transpose_w_kernel(const float* __restrict__ w) {
    int i = blockIdx.x * blockDim.x + threadIdx.x;
    if (i >= KTAPS * CIN * COUT) return;
    int o = i % COUT;
    int c = (i / COUT) % CIN;
    int k = i / (COUT * CIN);
    g_wT[i] = w[(o * CIN + c) * KTAPS + k];
}

__global__ void transpose_x_kernel(const float* __restrict__ x) {
    __shared__ float tile[32][33];
    int wT = blockIdx.x, cT = blockIdx.y, nh = blockIdx.z;
    int n = nh / HH, h = nh - n * HH;
    int tx = threadIdx.x, ty = threadIdx.y;
    #pragma unroll
    for (int i = 0; i < 4; ++i) {
        int c = cT * 32 + ty + i * 8;
        int w = wT * 32 + tx;
        if (w < WW)
            tile[ty + i * 8][tx] = x[((n * CIN + c) * HH + h) * WW + w];
    }
    __syncthreads();
    #pragma unroll
    for (int i = 0; i < 4; ++i) {
        int w = wT * 32 + ty + i * 8;
        int c = cT * 32 + tx;
        if (w < WW)
            g_xn[((n * HH + h) * WW + w) * CIN + c] = tile[tx][ty + i * 8];
    }
}

__device__ __forceinline__ u64 dup2(float a) {
    u64 r;
    asm("mov.b64 %0, {%1, %1};" : "=l"(r) : "f"(a));
    return r;
}
__device__ __forceinline__ void ffma2(u64& d, u64 a, u64 b) {
    asm("fma.rn.f32x2 %0, %1, %2, %0;" : "+l"(d) : "l"(a), "l"(b));
}
__device__ __forceinline__ void unpack2(float& lo, float& hi, u64 v) {
    asm("mov.b64 {%0, %1}, %2;" : "=f"(lo), "=f"(hi) : "l"(v));
}
__device__ __forceinline__ void cp_async16(void* smem_dst, const void* gmem_src) {
    unsigned sa = (unsigned)__cvta_generic_to_shared(smem_dst);
    asm volatile("cp.async.ca.shared.global [%0], [%1], 16;" :: "r"(sa), "l"(gmem_src));
}
__device__ __forceinline__ void cp_commit() {
    asm volatile("cp.async.commit_group;" ::: "memory");
}
__device__ __forceinline__ void cp_wait0() {
    asm volatile("cp.async.wait_group 0;" ::: "memory");
}

__device__ __forceinline__ void calc_taps(int pg, int k,
                                          const float* __restrict__ offset,
                                          const float* __restrict__ mask,
                                          int* tb, float* tw) {
    int n = pg / HWSZ;
    int hw = pg - n * HWSZ;
    int h = hw / WW;
    int w = hw - h * WW;
    float dy = offset[((n * 18 + 2 * k    ) * HH + h) * WW + w];
    float dx = offset[((n * 18 + 2 * k + 1) * HH + h) * WW + w];
    float m  = mask  [((n * 9  + k        ) * HH + h) * WW + w];
    float py = dy + (float)(k / 3) + (float)(h - 1);
    float px = dx + (float)(k % 3) + (float)(w - 1);
    float y0f = floorf(py), x0f = floorf(px);
    float wy1 = py - y0f, wx1 = px - x0f;
    float wy0 = 1.0f - wy1, wx0 = 1.0f - wx1;
    int y0 = (int)y0f, x0 = (int)x0f;
    float w4[4] = { wy0 * wx0, wy0 * wx1, wy1 * wx0, wy1 * wx1 };
    #pragma unroll
    for (int t = 0; t < 4; ++t) {
        int yy = y0 + (t >> 1);
        int xx = x0 + (t & 1);
        bool valid = (yy >= 0) && (yy < HH) && (xx >= 0) && (xx < WW);
        int yc = min(max(yy, 0), HH - 1);
        int xc = min(max(xx, 0), WW - 1);
        tb[t] = ((n * HH + yc) * WW + xc) * CIN;
        tw[t] = valid ? w4[t] * m : 0.0f;
    }
}

__global__ __launch_bounds__(NT, 2) void mdcn_kernel(
    const float* __restrict__ offset,
    const float* __restrict__ mask,
    const float* __restrict__ bias,
    float* __restrict__ out)
{
    __shared__ float As[2][BM][AP];     // 12 KB
    __shared__ float Bs[2][BK][BN];     // 32 KB

    const int p0  = blockIdx.x * BM;
    const int tid = threadIdx.x;
    const int tx  = tid & 31;           // cout group (8 couts)
    const int ty  = tid >> 5;           // pixel group (8 pixels)
    const int pA  = tid >> 2;           // gather pixel
    const int cqA = tid & 3;            // gather cin quad
    const int pgA = p0 + pA;

    int   tb[4];
    float twt[4];
    float4 rA[4];

    u64 acc[8][4];
    #pragma unroll
    for (int r = 0; r < 8; ++r)
        #pragma unroll
        for (int j = 0; j < 4; ++j) acc[r][j] = 0ULL;

    // ---- Prologue: prefetch step 0 ----
    calc_taps(pgA, 0, offset, mask, tb, twt);
    {
        const float* src = &g_wT[0];
        #pragma unroll
        for (int t = 0; t < 4; ++t)
            cp_async16(&Bs[0][0][0] + (tid + t * NT) * 4, src + (tid + t * NT) * 4);
        cp_commit();
        int c = cqA * 4;
        #pragma unroll
        for (int i = 0; i < 4; ++i)
            rA[i] = *(const float4*)&g_xn[tb[i] + c];
    }

    for (int step = 0; step < NSTEP; ++step) {
        const int buf = step & 1;

        // ---- store prefetched A (combine bilinear) ----
        {
            float4 v;
            v.x = fmaf(twt[3], rA[3].x, fmaf(twt[2], rA[2].x, fmaf(twt[1], rA[1].x, twt[0] * rA[0].x)));
            v.y = fmaf(twt[3], rA[3].y, fmaf(twt[2], rA[2].y, fmaf(twt[1], rA[1].y, twt[0] * rA[0].y)));
            v.z = fmaf(twt[3], rA[3].z, fmaf(twt[2], rA[2].z, fmaf(twt[1], rA[1].z, twt[0] * rA[0].z)));
            v.w = fmaf(twt[3], rA[3].w, fmaf(twt[2], rA[2].w, fmaf(twt[1], rA[1].w, twt[0] * rA[0].w)));
            *(float4*)&As[buf][pA][cqA * 4] = v;
        }
        cp_wait0();
        __syncthreads();

        // ---- prefetch step+1 ----
        if (step + 1 < NSTEP) {
            int k2 = (step + 1) >> 4;
            int c0 = ((step + 1) & 15) * BK;
            if (((step + 1) & 15) == 0)
                calc_taps(pgA, k2, offset, mask, tb, twt);
            const float* src = &g_wT[(k2 * CIN + c0) * COUT];
            float* dst = &Bs[buf ^ 1][0][0];
            #pragma unroll
            for (int t = 0; t < 4; ++t)
                cp_async16(dst + (tid + t * NT) * 4, src + (tid + t * NT) * 4);
            cp_commit();
            int c = c0 + cqA * 4;
            #pragma unroll
            for (int i = 0; i < 4; ++i)
                rA[i] = *(const float4*)&g_xn[tb[i] + c];
        }

        // ---- compute: 8x8 microtile with f32x2 packed FMA ----
        #pragma unroll
        for (int kk = 0; kk < BK; kk += 2) {
            const ulonglong2* bp0 = (const ulonglong2*)&Bs[buf][kk    ][tx * 8];
            const ulonglong2* bp1 = (const ulonglong2*)&Bs[buf][kk + 1][tx * 8];
            ulonglong2 bA0 = bp0[0], bB0 = bp0[1];
            ulonglong2 bA1 = bp1[0], bB1 = bp1[1];
            u64 bv0[4] = { bA0.x, bA0.y, bB0.x, bB0.y };
            u64 bv1[4] = { bA1.x, bA1.y, bB1.x, bB1.y };
            #pragma unroll
            for (int r = 0; r < 8; ++r) {
                float2 a2 = *(const float2*)&As[buf][ty * 8 + r][kk];
                u64 ad0 = dup2(a2.x);
                #pragma unroll
                for (int j = 0; j < 4; ++j) ffma2(acc[r][j], ad0, bv0[j]);
                u64 ad1 = dup2(a2.y);
                #pragma unroll
                for (int j = 0; j < 4; ++j) ffma2(acc[r][j], ad1, bv1[j]);
            }
        }
    }

    // ---- Epilogue ----
    #pragma unroll
    for (int r = 0; r < 8; ++r) {
        int pg = p0 + ty * 8 + r;
        int n  = pg / HWSZ;
        int hw = pg - n * HWSZ;
        long base = (long)n * COUT * HWSZ + hw;
        #pragma unroll
        for (int j = 0; j < 4; ++j) {
            float lo, hi;
            unpack2(lo, hi, acc[r][j]);
            int o = tx * 8 + j * 2;
            out[base + (long)o * HWSZ]       = lo + bias[o];
            out[base + (long)(o + 1) * HWSZ] = hi + bias[o + 1];
        }
    }
}

extern "C" void kernel_launch(void* const* d_in, const int* in_sizes, int n_in,
                              void* d_out, int out_size) {
    const float* x      = (const float*)d_in[0];
    const float* offset = (const float*)d_in[1];
    const float* mask   = (const float*)d_in[2];
    const float* weight = (const float*)d_in[3];
    const float* bias   = (const float*)d_in[4];
    float* out = (float*)d_out;

    transpose_w_kernel<<<(KTAPS * CIN * COUT + 255) / 256, 256>>>(weight);
    {
        dim3 grid(2, 8, NB * HH);
        dim3 block(32, 8);
        transpose_x_kernel<<<grid, block>>>(x);
    }
    mdcn_kernel<<<MTOT / BM, NT>>>(offset, mask, bias, out);
}

// round 9
// speedup vs baseline: 6.3534x; 2.3983x over previous
#include <cuda_runtime.h>
#include <cuda_bf16.h>
#include <cstdint>

// Modulated deformable conv: deformable-im2col + tf32 mma.sync GEMM.
//   M = N*H*W = 25088 pixels, Ngemm = Cout = 256, Kgemm = 9*256 = 2304.
// (tcgen05 is unusable here: harness PTX stage targets sm_103 without 'a'.)
// CTA: 64 px x 256 cout, TK=32. 8 warps (2x4), warp tile 32x64 via m16n8k8.

#define CIN   256
#define COUT  256
#define HH    56
#define WW    56
#define NB    8
#define KTAPS 9
#define HWSZ  (HH*WW)          // 3136 = 49*64
#define MTOT  (NB*HWSZ)        // 25088

#define BM 64
#define BN 256
#define TK 32
#define NT 256
#define NSTEP (KTAPS*CIN/TK)   // 72
#define NCHUNK (CIN/TK)        // 8

#define AP 36                  // As row stride (floats): bank = (4r+c)%32, conflict-free
#define BP 260                 // Bs row stride (floats): bank = (4r+c)%32, conflict-free

#define SM_A      0
#define ABUF      (BM*AP*4)            // 9216
#define SM_B      (2*ABUF)             // 18432
#define BBUF      (TK*BP*4)            // 33280
#define SM_TOTAL  (SM_B + 2*BBUF)      // 84992

typedef unsigned int u32;

__device__ float g_xn[NB * HH * WW * CIN];          // NHWC fp32, 25.7 MB
__device__ u32   g_wB[KTAPS * NCHUNK * TK * COUT];  // tf32 [k][chunk][cin32][cout256]

// ---------------- helpers ----------------
__device__ __forceinline__ u32 cvt_tf32(float f) {
    u32 r;
    asm("cvt.rna.tf32.f32 %0, %1;" : "=r"(r) : "f"(f));
    return r;
}
__device__ __forceinline__ void cp_async16(void* smem_dst, const void* gmem_src) {
    u32 sa = (u32)__cvta_generic_to_shared(smem_dst);
    asm volatile("cp.async.ca.shared.global [%0], [%1], 16;" :: "r"(sa), "l"(gmem_src));
}
__device__ __forceinline__ void cp_commit() { asm volatile("cp.async.commit_group;" ::: "memory"); }
__device__ __forceinline__ void cp_wait0()  { asm volatile("cp.async.wait_group 0;" ::: "memory"); }

__device__ __forceinline__ void mma_tf32(float* d, const u32* a, u32 b0, u32 b1) {
    asm volatile(
        "mma.sync.aligned.m16n8k8.row.col.f32.tf32.tf32.f32 "
        "{%0,%1,%2,%3}, {%4,%5,%6,%7}, {%8,%9}, {%0,%1,%2,%3};"
        : "+f"(d[0]), "+f"(d[1]), "+f"(d[2]), "+f"(d[3])
        : "r"(a[0]), "r"(a[1]), "r"(a[2]), "r"(a[3]), "r"(b0), "r"(b1));
}

// ---------------- prep kernels ----------------
__global__ void prep_w_kernel(const float* __restrict__ w) {
    int i = blockIdx.x * blockDim.x + threadIdx.x;
    if (i >= KTAPS * CIN * COUT) return;
    int k = i / (CIN * COUT);
    int r = i - k * (CIN * COUT);
    int o = r / CIN;
    int c = r - o * CIN;
    int chunk = c >> 5, cl = c & 31;
    g_wB[((k * NCHUNK + chunk) * TK + cl) * COUT + o] = cvt_tf32(w[(o * CIN + c) * KTAPS + k]);
}

__global__ void transpose_x_kernel(const float* __restrict__ x) {
    __shared__ float tile[32][33];
    int wT = blockIdx.x, cT = blockIdx.y, nh = blockIdx.z;
    int n = nh / HH, h = nh - n * HH;
    int tx = threadIdx.x, ty = threadIdx.y;
    #pragma unroll
    for (int i = 0; i < 4; ++i) {
        int c = cT * 32 + ty + i * 8;
        int w = wT * 32 + tx;
        if (w < WW)
            tile[ty + i * 8][tx] = x[((n * CIN + c) * HH + h) * WW + w];
    }
    __syncthreads();
    #pragma unroll
    for (int i = 0; i < 4; ++i) {
        int w = wT * 32 + ty + i * 8;
        int c = cT * 32 + tx;
        if (w < WW)
            g_xn[((n * HH + h) * WW + w) * CIN + c] = tile[tx][ty + i * 8];
    }
}

// ---------------- main kernel ----------------
__device__ __forceinline__ void calc_taps(int pg, int k,
                                          const float* __restrict__ offset,
                                          const float* __restrict__ mask,
                                          int* tb, float* tw) {
    int n = pg / HWSZ;
    int hw = pg - n * HWSZ;
    int h = hw / WW;
    int w = hw - h * WW;
    float dy = offset[((n * 18 + 2 * k    ) * HH + h) * WW + w];
    float dx = offset[((n * 18 + 2 * k + 1) * HH + h) * WW + w];
    float m  = mask  [((n * 9  + k        ) * HH + h) * WW + w];
    float py = dy + (float)(k / 3) + (float)(h - 1);
    float px = dx + (float)(k % 3) + (float)(w - 1);
    float y0f = floorf(py), x0f = floorf(px);
    float wy1 = py - y0f, wx1 = px - x0f;
    float wy0 = 1.0f - wy1, wx0 = 1.0f - wx1;
    int y0 = (int)y0f, x0 = (int)x0f;
    float w4[4] = { wy0 * wx0, wy0 * wx1, wy1 * wx0, wy1 * wx1 };
    #pragma unroll
    for (int t = 0; t < 4; ++t) {
        int yy = y0 + (t >> 1);
        int xx = x0 + (t & 1);
        bool valid = (yy >= 0) && (yy < HH) && (xx >= 0) && (xx < WW);
        int yc = min(max(yy, 0), HH - 1);
        int xc = min(max(xx, 0), WW - 1);
        tb[t] = ((n * HH + yc) * WW + xc) * CIN;
        tw[t] = valid ? w4[t] * m : 0.0f;
    }
}

__global__ __launch_bounds__(NT, 2) void mdcn_kernel(
    const float* __restrict__ offset,
    const float* __restrict__ mask,
    const float* __restrict__ bias,
    float* __restrict__ out)
{
    extern __shared__ char smem[];
    const int tid = threadIdx.x;
    const int wid = tid >> 5;
    const int lid = tid & 31;
    const int p0 = blockIdx.x * BM;

    const int wm = wid & 1;          // M warp (2)
    const int wn = wid >> 1;         // N warp (4)
    const int fr = lid >> 2;         // fragment row group 0..7
    const int fc = lid & 3;          // fragment col group 0..3

    const int pA = tid >> 2;         // gather pixel 0..63
    const int cq = tid & 3;          // gather quad

    int   tb[4];
    float tw[4];

    float acc[2][8][4];
    #pragma unroll
    for (int mt = 0; mt < 2; ++mt)
        #pragma unroll
        for (int nt = 0; nt < 8; ++nt)
            #pragma unroll
            for (int j = 0; j < 4; ++j) acc[mt][nt][j] = 0.0f;

    for (int step = 0; step < NSTEP; ++step) {
        const int buf = step & 1;
        const int k = step >> 3;
        const int chunk = step & 7;
        const int c0 = chunk * TK;

        if (chunk == 0)
            calc_taps(p0 + pA, k, offset, mask, tb, tw);

        // ---- B tile: cp.async 32KB of pre-swizzled tf32 weights ----
        {
            const char* src = (const char*)&g_wB[(k * NCHUNK + chunk) * (TK * COUT)];
            char* dstb = smem + SM_B + buf * BBUF;
            #pragma unroll
            for (int t = 0; t < 8; ++t) {
                int id = tid + t * NT;               // 0..2047
                int row = id >> 6, off = id & 63;
                cp_async16(dstb + row * (BP * 4) + off * 16, src + id * 16);
            }
            cp_commit();
        }

        // ---- A tile: deformable gather, fp32 bilinear -> tf32, padded store ----
        {
            char* abuf = smem + SM_A + buf * ABUF;
            #pragma unroll
            for (int half = 0; half < 2; ++half) {
                int c = c0 + cq * 4 + half * 16;
                float4 v0 = *(const float4*)&g_xn[tb[0] + c];
                float4 v1 = *(const float4*)&g_xn[tb[1] + c];
                float4 v2 = *(const float4*)&g_xn[tb[2] + c];
                float4 v3 = *(const float4*)&g_xn[tb[3] + c];
                uint4 r;
                r.x = cvt_tf32(fmaf(tw[3], v3.x, fmaf(tw[2], v2.x, fmaf(tw[1], v1.x, tw[0] * v0.x))));
                r.y = cvt_tf32(fmaf(tw[3], v3.y, fmaf(tw[2], v2.y, fmaf(tw[1], v1.y, tw[0] * v0.y))));
                r.z = cvt_tf32(fmaf(tw[3], v3.z, fmaf(tw[2], v2.z, fmaf(tw[1], v1.z, tw[0] * v0.z))));
                r.w = cvt_tf32(fmaf(tw[3], v3.w, fmaf(tw[2], v2.w, fmaf(tw[1], v1.w, tw[0] * v0.w))));
                *(uint4*)(abuf + pA * (AP * 4) + cq * 16 + half * 64) = r;
            }
        }

        cp_wait0();
        __syncthreads();

        // ---- compute: 8 warps x (2 Mtiles x 8 Ntiles) m16n8k8 tf32 ----
        {
            const u32* As = (const u32*)(smem + SM_A + buf * ABUF);
            const u32* Bs = (const u32*)(smem + SM_B + buf * BBUF);
            #pragma unroll
            for (int ks = 0; ks < 4; ++ks) {
                u32 a[2][4];
                #pragma unroll
                for (int mt = 0; mt < 2; ++mt) {
                    int px = wm * 32 + mt * 16 + fr;
                    int ci = ks * 8 + fc;
                    a[mt][0] = As[px * AP + ci];
                    a[mt][1] = As[(px + 8) * AP + ci];
                    a[mt][2] = As[px * AP + ci + 4];
                    a[mt][3] = As[(px + 8) * AP + ci + 4];
                }
                #pragma unroll
                for (int nt = 0; nt < 8; ++nt) {
                    int col = wn * 64 + nt * 8 + fr;
                    int row = ks * 8 + fc;
                    u32 b0 = Bs[row * BP + col];
                    u32 b1 = Bs[(row + 4) * BP + col];
                    mma_tf32(acc[0][nt], a[0], b0, b1);
                    mma_tf32(acc[1][nt], a[1], b0, b1);
                }
            }
        }
        __syncthreads();
    }

    // ---- Epilogue ----
    const int n  = p0 / HWSZ;              // CTA never straddles images (3136 % 64 == 0)
    const int hw0 = p0 - n * HWSZ;
    #pragma unroll
    for (int nt = 0; nt < 8; ++nt) {
        int o0 = wn * 64 + nt * 8 + fc * 2;
        float b0 = __ldg(&bias[o0]);
        float b1 = __ldg(&bias[o0 + 1]);
        #pragma unroll
        for (int mt = 0; mt < 2; ++mt) {
            int hwA = hw0 + wm * 32 + mt * 16 + fr;
            long baseA = (long)(n * COUT + o0) * HWSZ + hwA;
            long baseB = baseA + 8;        // row +8
            out[baseA]            = acc[mt][nt][0] + b0;
            out[baseA + HWSZ]     = acc[mt][nt][1] + b1;
            out[baseB]            = acc[mt][nt][2] + b0;
            out[baseB + HWSZ]     = acc[mt][nt][3] + b1;
        }
    }
}

extern "C" void kernel_launch(void* const* d_in, const int* in_sizes, int n_in,
                              void* d_out, int out_size) {
    const float* x      = (const float*)d_in[0];
    const float* offset = (const float*)d_in[1];
    const float* mask   = (const float*)d_in[2];
    const float* weight = (const float*)d_in[3];
    const float* bias   = (const float*)d_in[4];
    float* out = (float*)d_out;

    cudaFuncSetAttribute(mdcn_kernel, cudaFuncAttributeMaxDynamicSharedMemorySize, SM_TOTAL);

    prep_w_kernel<<<(KTAPS * CIN * COUT + 255) / 256, 256>>>(weight);
    {
        dim3 grid(2, 8, NB * HH);
        dim3 block(32, 8);
        transpose_x_kernel<<<grid, block>>>(x);
    }
    mdcn_kernel<<<MTOT / BM, NT, SM_TOTAL>>>(offset, mask, bias, out);
}

// round 12
// speedup vs baseline: 7.0557x; 1.1105x over previous
#include <cuda_runtime.h>
#include <cuda_bf16.h>
#include <cstdint>

// Modulated deformable conv: deformable-im2col + tf32 mma.sync GEMM.
// R10: one-step-ahead register prefetch of the gather (LDG latency hidden
// behind MMA), B fragments pre-packed as XOR-swizzled u64 pairs (LDS.64).
//   M = 25088 px, N = 256 cout, K = 2304. CTA: 64 px x 256 cout, TK=32.

#define CIN   256
#define COUT  256
#define HH    56
#define WW    56
#define NB    8
#define KTAPS 9
#define HWSZ  (HH*WW)
#define MTOT  (NB*HWSZ)        // 25088

#define BM 64
#define BN 256
#define TK 32
#define NT 256
#define NSTEP (KTAPS*CIN/TK)   // 72
#define NCHUNK (CIN/TK)        // 8

#define AP 36                  // As row stride (floats), conflict-free frag loads

#define SM_A      0
#define ABUF      (BM*AP*4)            // 9216
#define SM_B      (2*ABUF)             // 18432
#define BBUF      (TK*BN*4)            // 32768 (u64-packed, no padding needed)
#define SM_TOTAL  (SM_B + 2*BBUF)      // 83968

typedef unsigned int u32;
typedef unsigned long long u64;

__device__ float g_xn[NB * HH * WW * CIN];          // NHWC fp32
__device__ u32   g_wB[KTAPS * NCHUNK * TK * COUT];  // tf32, u64-pair swizzled tiles

// ---------------- helpers ----------------
__device__ __forceinline__ u32 cvt_tf32(float f) {
    u32 r;
    asm("cvt.rna.tf32.f32 %0, %1;" : "=r"(r) : "f"(f));
    return r;
}
__device__ __forceinline__ void cp_async16(void* smem_dst, const void* gmem_src) {
    u32 sa = (u32)__cvta_generic_to_shared(smem_dst);
    asm volatile("cp.async.ca.shared.global [%0], [%1], 16;" :: "r"(sa), "l"(gmem_src));
}
__device__ __forceinline__ void cp_commit() { asm volatile("cp.async.commit_group;" ::: "memory"); }
__device__ __forceinline__ void cp_wait0()  { asm volatile("cp.async.wait_group 0;" ::: "memory"); }

__device__ __forceinline__ void mma_tf32(float* d, const u32* a, u32 b0, u32 b1) {
    asm volatile(
        "mma.sync.aligned.m16n8k8.row.col.f32.tf32.tf32.f32 "
        "{%0,%1,%2,%3}, {%4,%5,%6,%7}, {%8,%9}, {%0,%1,%2,%3};"
        : "+f"(d[0]), "+f"(d[1]), "+f"(d[2]), "+f"(d[3])
        : "r"(a[0]), "r"(a[1]), "r"(a[2]), "r"(a[3]), "r"(b0), "r"(b1));
}

// ---------------- prep kernels ----------------
// weight [Cout][Cin][3][3] -> per-(tap,chunk) tile of u64 pairs:
//   u64 slot i64 = col*16 + ((ks*4+fc) ^ ((col&3)<<2)); lo = row ks*8+fc, hi = +4
__global__ void prep_w_kernel(const float* __restrict__ w) {
    int i = blockIdx.x * blockDim.x + threadIdx.x;
    if (i >= KTAPS * CIN * COUT) return;
    int k = i / (CIN * COUT);
    int r = i - k * (CIN * COUT);
    int o = r / CIN;
    int c = r - o * CIN;
    int chunk = c >> 5, cl = c & 31;
    int ks = cl >> 3, rem = cl & 7;
    int fc = rem & 3, half = rem >> 2;
    int i64 = o * 16 + ((ks * 4 + fc) ^ ((o & 3) << 2));
    g_wB[(k * NCHUNK + chunk) * (TK * COUT) + i64 * 2 + half] =
        cvt_tf32(w[(o * CIN + c) * KTAPS + k]);
}

__global__ void transpose_x_kernel(const float* __restrict__ x) {
    __shared__ float tile[32][33];
    int wT = blockIdx.x, cT = blockIdx.y, nh = blockIdx.z;
    int n = nh / HH, h = nh - n * HH;
    int tx = threadIdx.x, ty = threadIdx.y;
    #pragma unroll
    for (int i = 0; i < 4; ++i) {
        int c = cT * 32 + ty + i * 8;
        int w = wT * 32 + tx;
        if (w < WW)
            tile[ty + i * 8][tx] = x[((n * CIN + c) * HH + h) * WW + w];
    }
    __syncthreads();
    #pragma unroll
    for (int i = 0; i < 4; ++i) {
        int w = wT * 32 + ty + i * 8;
        int c = cT * 32 + tx;
        if (w < WW)
            g_xn[((n * HH + h) * WW + w) * CIN + c] = tile[tx][ty + i * 8];
    }
}

// ---------------- main kernel ----------------
__device__ __forceinline__ void calc_taps(int pg, int k,
                                          const float* __restrict__ offset,
                                          const float* __restrict__ mask,
                                          int* tb, float* tw) {
    int n = pg / HWSZ;
    int hw = pg - n * HWSZ;
    int h = hw / WW;
    int w = hw - h * WW;
    float dy = offset[((n * 18 + 2 * k    ) * HH + h) * WW + w];
    float dx = offset[((n * 18 + 2 * k + 1) * HH + h) * WW + w];
    float m  = mask  [((n * 9  + k        ) * HH + h) * WW + w];
    float py = dy + (float)(k / 3) + (float)(h - 1);
    float px = dx + (float)(k % 3) + (float)(w - 1);
    float y0f = floorf(py), x0f = floorf(px);
    float wy1 = py - y0f, wx1 = px - x0f;
    float wy0 = 1.0f - wy1, wx0 = 1.0f - wx1;
    int y0 = (int)y0f, x0 = (int)x0f;
    float w4[4] = { wy0 * wx0, wy0 * wx1, wy1 * wx0, wy1 * wx1 };
    #pragma unroll
    for (int t = 0; t < 4; ++t) {
        int yy = y0 + (t >> 1);
        int xx = x0 + (t & 1);
        bool valid = (yy >= 0) && (yy < HH) && (xx >= 0) && (xx < WW);
        int yc = min(max(yy, 0), HH - 1);
        int xc = min(max(xx, 0), WW - 1);
        tb[t] = ((n * HH + yc) * WW + xc) * CIN;
        tw[t] = valid ? w4[t] * m : 0.0f;
    }
}

__global__ __launch_bounds__(NT, 2) void mdcn_kernel(
    const float* __restrict__ offset,
    const float* __restrict__ mask,
    const float* __restrict__ bias,
    float* __restrict__ out)
{
    extern __shared__ char smem[];
    const int tid = threadIdx.x;
    const int wid = tid >> 5;
    const int lid = tid & 31;
    const int p0 = blockIdx.x * BM;

    const int wm = wid & 1;          // M warp (2)
    const int wn = wid >> 1;         // N warp (4)
    const int fr = lid >> 2;         // frag row group 0..7
    const int fc = lid & 3;          // frag col group 0..3

    const int pA = tid >> 2;         // gather pixel 0..63
    const int cq = tid & 3;          // gather quad

    int   tb[4];
    float tw[4];
    float4 rA[2][4];                 // prefetched gather corners (2 halves x 4 corners)

    float acc[2][8][4];
    #pragma unroll
    for (int mt = 0; mt < 2; ++mt)
        #pragma unroll
        for (int nt = 0; nt < 8; ++nt)
            #pragma unroll
            for (int j = 0; j < 4; ++j) acc[mt][nt][j] = 0.0f;

    // ---- Prologue: taps + gather prefetch for step 0 ----
    calc_taps(p0 + pA, 0, offset, mask, tb, tw);
    #pragma unroll
    for (int half = 0; half < 2; ++half) {
        int c = cq * 4 + half * 16;
        #pragma unroll
        for (int t = 0; t < 4; ++t)
            rA[half][t] = *(const float4*)&g_xn[tb[t] + c];
    }

    for (int step = 0; step < NSTEP; ++step) {
        const int buf = step & 1;

        // ---- combine prefetched corners -> tf32 -> As[buf] ----
        {
            char* abuf = smem + SM_A + buf * ABUF;
            #pragma unroll
            for (int half = 0; half < 2; ++half) {
                float4 v0 = rA[half][0], v1 = rA[half][1];
                float4 v2 = rA[half][2], v3 = rA[half][3];
                uint4 r;
                r.x = cvt_tf32(fmaf(tw[3], v3.x, fmaf(tw[2], v2.x, fmaf(tw[1], v1.x, tw[0] * v0.x))));
                r.y = cvt_tf32(fmaf(tw[3], v3.y, fmaf(tw[2], v2.y, fmaf(tw[1], v1.y, tw[0] * v0.y))));
                r.z = cvt_tf32(fmaf(tw[3], v3.z, fmaf(tw[2], v2.z, fmaf(tw[1], v1.z, tw[0] * v0.z))));
                r.w = cvt_tf32(fmaf(tw[3], v3.w, fmaf(tw[2], v2.w, fmaf(tw[1], v1.w, tw[0] * v0.w))));
                *(uint4*)(abuf + pA * (AP * 4) + cq * 16 + half * 64) = r;
            }
        }

        // ---- B tile: cp.async 32KB pre-packed tile ----
        {
            const int k = step >> 3;
            const int chunk = step & 7;
            const char* src = (const char*)&g_wB[(k * NCHUNK + chunk) * (TK * COUT)];
            char* dstb = smem + SM_B + buf * BBUF;
            #pragma unroll
            for (int t = 0; t < 8; ++t) {
                int id = tid + t * NT;
                cp_async16(dstb + id * 16, src + id * 16);
            }
            cp_commit();
        }

        // ---- prefetch gather for step+1 (overlaps wait + MMA) ----
        if (step + 1 < NSTEP) {
            if (((step + 1) & 7) == 0)
                calc_taps(p0 + pA, (step + 1) >> 3, offset, mask, tb, tw);
            int c0n = ((step + 1) & 7) * TK;
            #pragma unroll
            for (int half = 0; half < 2; ++half) {
                int c = c0n + cq * 4 + half * 16;
                #pragma unroll
                for (int t = 0; t < 4; ++t)
                    rA[half][t] = *(const float4*)&g_xn[tb[t] + c];
            }
        }

        cp_wait0();
        __syncthreads();

        // ---- compute: 8 warps x (2 Mtiles x 8 Ntiles) m16n8k8 tf32 ----
        {
            const u32* As = (const u32*)(smem + SM_A + buf * ABUF);
            const u64* Bs64 = (const u64*)(smem + SM_B + buf * BBUF);
            const int cbase = (wn * 64 + fr) * 16;
            #pragma unroll
            for (int ks = 0; ks < 4; ++ks) {
                u32 a[2][4];
                #pragma unroll
                for (int mt = 0; mt < 2; ++mt) {
                    int px = wm * 32 + mt * 16 + fr;
                    int ci = ks * 8 + fc;
                    a[mt][0] = As[px * AP + ci];
                    a[mt][1] = As[(px + 8) * AP + ci];
                    a[mt][2] = As[px * AP + ci + 4];
                    a[mt][3] = As[(px + 8) * AP + ci + 4];
                }
                const int C = (ks * 4 + fc) ^ ((fr & 3) << 2);
                #pragma unroll
                for (int nt = 0; nt < 8; ++nt) {
                    u64 b = Bs64[cbase + nt * 128 + C];
                    u32 b0 = (u32)b, b1 = (u32)(b >> 32);
                    mma_tf32(acc[0][nt], a[0], b0, b1);
                    mma_tf32(acc[1][nt], a[1], b0, b1);
                }
            }
        }
        __syncthreads();
    }

    // ---- Epilogue ----
    const int n  = p0 / HWSZ;              // CTA never straddles images
    const int hw0 = p0 - n * HWSZ;
    #pragma unroll
    for (int nt = 0; nt < 8; ++nt) {
        int o0 = wn * 64 + nt * 8 + fc * 2;
        float b0 = __ldg(&bias[o0]);
        float b1 = __ldg(&bias[o0 + 1]);
        #pragma unroll
        for (int mt = 0; mt < 2; ++mt) {
            int hwA = hw0 + wm * 32 + mt * 16 + fr;
            long baseA = (long)(n * COUT + o0) * HWSZ + hwA;
            long baseB = baseA + 8;
            out[baseA]        = acc[mt][nt][0] + b0;
            out[baseA + HWSZ] = acc[mt][nt][1] + b1;
            out[baseB]        = acc[mt][nt][2] + b0;
            out[baseB + HWSZ] = acc[mt][nt][3] + b1;
        }
    }
}

extern "C" void kernel_launch(void* const* d_in, const int* in_sizes, int n_in,
                              void* d_out, int out_size) {
    const float* x      = (const float*)d_in[0];
    const float* offset = (const float*)d_in[1];
    const float* mask   = (const float*)d_in[2];
    const float* weight = (const float*)d_in[3];
    const float* bias   = (const float*)d_in[4];
    float* out = (float*)d_out;

    cudaFuncSetAttribute(mdcn_kernel, cudaFuncAttributeMaxDynamicSharedMemorySize, SM_TOTAL);

    prep_w_kernel<<<(KTAPS * CIN * COUT + 255) / 256, 256>>>(weight);
    {
        dim3 grid(2, 8, NB * HH);
        dim3 block(32, 8);
        transpose_x_kernel<<<grid, block>>>(x);
    }
    mdcn_kernel<<<MTOT / BM, NT, SM_TOTAL>>>(offset, mask, bias, out);
}